// round 1
// baseline (speedup 1.0000x reference)
#include <cuda_runtime.h>

typedef unsigned long long u64;

#define BN 16
#define CN 4
#define HN 512
#define WN 512
#define HID 32
#define TILE 32
#define RAD 3
#define SUMH (TILE + 2*RAD)   /* 38 rows of horizontal sums (vertical halo) */
#define NCP (TILE/2)          /* 16 column pairs */

/* ---------------- f32x2 helpers (sm_100+ packed fp32) ---------------- */
__device__ __forceinline__ u64 pk(float lo, float hi){ u64 r; asm("mov.b64 %0,{%1,%2};":"=l"(r):"f"(lo),"f"(hi)); return r; }
__device__ __forceinline__ void upk(u64 v,float&lo,float&hi){ asm("mov.b64 {%0,%1},%2;":"=f"(lo),"=f"(hi):"l"(v)); }
__device__ __forceinline__ u64 dup2(float x){ u64 r; asm("mov.b64 %0,{%1,%1};":"=l"(r):"f"(x)); return r; }
__device__ __forceinline__ u64 ffma2(u64 a,u64 b,u64 c){ u64 d; asm("fma.rn.f32x2 %0,%1,%2,%3;":"=l"(d):"l"(a),"l"(b),"l"(c)); return d; }
__device__ __forceinline__ u64 fadd2(u64 a,u64 b){ u64 d; asm("add.rn.f32x2 %0,%1,%2;":"=l"(d):"l"(a),"l"(b)); return d; }
__device__ __forceinline__ u64 fmul2(u64 a,u64 b){ u64 d; asm("mul.rn.f32x2 %0,%1,%2;":"=l"(d):"l"(a),"l"(b)); return d; }
__device__ __forceinline__ float rcpf(float x){ float r; asm("rcp.approx.ftz.f32 %0,%1;":"=f"(r):"f"(x)); return r; }
__device__ __forceinline__ float ex2f(float x){ float r; asm("ex2.approx.ftz.f32 %0,%1;":"=f"(r):"f"(x)); return r; }

/* exact-gelu on a packed pair: x*0.5*(1+erf(x/sqrt2)), erf via A&S 7.1.26
   (abs err 1.5e-7 — far below the 1e-3 test threshold). */
__device__ __forceinline__ u64 gelu2(u64 h){
  const u64 SGN = 0x8000000080000000ULL;
  const u64 ABS = 0x7FFFFFFF7FFFFFFFULL;
  u64 az  = h & ABS;
  u64 azs = fmul2(az, dup2(0.70710678118654752f));     /* |z| = |h|/sqrt2 */
  u64 den = ffma2(azs, dup2(0.3275911f), dup2(1.0f));
  float d0,d1; upk(den,d0,d1);
  u64 t = pk(rcpf(d0), rcpf(d1));
  u64 P = ffma2(dup2(1.061405429f), t, dup2(-1.453152027f));
  P = ffma2(P, t, dup2(1.421413741f));
  P = ffma2(P, t, dup2(-0.284496736f));
  P = ffma2(P, t, dup2(0.254829592f));
  P = fmul2(P, t);
  u64 h2 = fmul2(h, h);
  u64 ea = fmul2(h2, dup2(-0.72134752044448170f));     /* -z^2*log2(e) */
  float e0,e1; upk(ea,e0,e1);
  u64 E  = pk(ex2f(e0), ex2f(e1));
  u64 PE = fmul2(P, E);
  u64 y  = ffma2(PE, dup2(-1.0f), dup2(1.0f));         /* erf(|z|) in [0,1] */
  u64 er = y | (h & SGN);                              /* copysign */
  u64 u  = ffma2(er, dup2(0.5f), dup2(0.5f));          /* 0.5*(1+erf) */
  return fmul2(h, u);
}

__device__ __forceinline__ int refl(int i, int n){
  if (i < 0) i = -i;
  if (i >= n) i = 2*n - 2 - i;
  return i;
}

__global__ void __launch_bounds__(256,2)
lee_kernel(const float* __restrict__ x, const float* __restrict__ W1,
           const float* __restrict__ b1, const float* __restrict__ W2,
           const float* __restrict__ b2, float* __restrict__ out)
{
  __shared__ __align__(16) float hs[CN][SUMH][TILE];   /* horiz 7-sum of x   */
  __shared__ __align__(16) float hq[CN][SUMH][TILE];   /* horiz 7-sum of x^2 */
  __shared__ __align__(16) u64 w1d[HID][16];           /* dup-packed weights */
  __shared__ __align__(16) u64 w2d[HID][CN];
  __shared__ __align__(16) u64 b1d[HID];
  __shared__ __align__(16) u64 b2d[CN];

  const int tid = threadIdx.x;
  const int x0 = blockIdx.x * TILE;
  const int y0 = blockIdx.y * TILE;
  const int b  = blockIdx.z;
  const float* xb = x + (size_t)b * CN * HN * WN;

  /* ---- weights -> dup-packed shared ---- */
  for (int i = tid; i < HID*16; i += 256){ float v = W1[i]; w1d[i>>4][i&15] = pk(v,v); }
  if (tid < HID*CN){ int k = tid >> 2, c = tid & 3; float v = W2[c*HID + k]; w2d[k][c] = pk(v,v); }
  if (tid < HID){ float v = b1[tid]; b1d[tid] = pk(v,v); }
  if (tid < CN){ float v = b2[tid]; b2d[tid] = pk(v,v); }

  /* ---- stage 1: horizontal 7-window sums (reflect-padded reads, L1-hit) ---- */
  for (int t = tid; t < CN*SUMH*NCP; t += 256){
    int cp = t & (NCP-1);
    int r  = (t / NCP) % SUMH;
    int c  = t / (NCP*SUMH);
    int gy = refl(y0 - RAD + r, HN);
    const float* row = xb + ((size_t)c*HN + gy) * WN;
    int gx0 = x0 - RAD + 2*cp;
    float v[8];
    #pragma unroll
    for (int d = 0; d < 8; d++) v[d] = __ldg(&row[refl(gx0 + d, WN)]);
    float s0 = v[0]+v[1]+v[2]+v[3]+v[4]+v[5]+v[6];
    float s1 = s0 - v[0] + v[7];
    float q0 = 0.f;
    #pragma unroll
    for (int d = 0; d < 7; d++) q0 = fmaf(v[d], v[d], q0);
    float q1 = fmaf(v[7], v[7], q0 - v[0]*v[0]);
    hs[c][r][2*cp] = s0; hs[c][r][2*cp+1] = s1;
    hq[c][r][2*cp] = q0; hq[c][r][2*cp+1] = q1;
  }
  __syncthreads();

  /* ---- stage 2: vertical sums + per-pixel MLP, two packed pixel-pairs/thread ---- */
  const int tpx  = tid & (NCP-1);     /* column pair 0..15 */
  const int tpy  = tid >> 4;          /* rows tpy and tpy+16 */
  const int col0 = x0 + 2*tpx;
  const u64 INV49 = dup2(1.0f/49.0f);

  u64 featA[16], featB[16];
  #pragma unroll
  for (int c = 0; c < CN; c++){
    u64 sA=0, qA=0, sB=0, qB=0;
    #pragma unroll
    for (int dy = 0; dy < 7; dy++){
      sA = fadd2(sA, *(const u64*)&hs[c][tpy+dy][2*tpx]);
      qA = fadd2(qA, *(const u64*)&hq[c][tpy+dy][2*tpx]);
      sB = fadd2(sB, *(const u64*)&hs[c][tpy+16+dy][2*tpx]);
      qB = fadd2(qB, *(const u64*)&hq[c][tpy+16+dy][2*tpx]);
    }
    u64 meanA = fmul2(sA, INV49), msqA = fmul2(qA, INV49);
    u64 meanB = fmul2(sB, INV49), msqB = fmul2(qB, INV49);
    u64 varA = ffma2(meanA, meanA ^ 0x8000000080000000ULL, msqA);
    u64 varB = ffma2(meanB, meanB ^ 0x8000000080000000ULL, msqB);
    { float a0,a1; upk(varA,a0,a1); varA = pk(fmaxf(a0,0.f), fmaxf(a1,0.f)); }
    { float a0,a1; upk(varB,a0,a1); varB = pk(fmaxf(a0,0.f), fmaxf(a1,0.f)); }
    featA[c]    = *(const u64*)(xb + ((size_t)c*HN + y0 + tpy     )*WN + col0);
    featB[c]    = *(const u64*)(xb + ((size_t)c*HN + y0 + tpy + 16)*WN + col0);
    featA[4+c]  = meanA;  featB[4+c]  = meanB;
    featA[8+c]  = varA;   featB[8+c]  = varB;
    featA[12+c] = msqA;   featB[12+c] = msqB;
  }

  u64 outA[CN], outB[CN];
  #pragma unroll
  for (int c = 0; c < CN; c++){
    outA[c] = fadd2(featA[c], b2d[c]);   /* out = x + b2 + W2*gelu(...) */
    outB[c] = fadd2(featB[c], b2d[c]);
  }

  #pragma unroll 2
  for (int k = 0; k < HID; k++){
    u64 aA = b1d[k], aB = b1d[k];
    const ulonglong2* wr = (const ulonglong2*)&w1d[k][0];
    #pragma unroll
    for (int jj = 0; jj < 8; jj++){
      ulonglong2 w = wr[jj];
      aA = ffma2(featA[2*jj],   w.x, aA);
      aB = ffma2(featB[2*jj],   w.x, aB);
      aA = ffma2(featA[2*jj+1], w.y, aA);
      aB = ffma2(featB[2*jj+1], w.y, aB);
    }
    u64 gA = gelu2(aA), gB = gelu2(aB);
    const ulonglong2* w2r = (const ulonglong2*)&w2d[k][0];
    ulonglong2 wa = w2r[0], wb = w2r[1];
    outA[0] = ffma2(gA, wa.x, outA[0]);  outB[0] = ffma2(gB, wa.x, outB[0]);
    outA[1] = ffma2(gA, wa.y, outA[1]);  outB[1] = ffma2(gB, wa.y, outB[1]);
    outA[2] = ffma2(gA, wb.x, outA[2]);  outB[2] = ffma2(gB, wb.x, outB[2]);
    outA[3] = ffma2(gA, wb.y, outA[3]);  outB[3] = ffma2(gB, wb.y, outB[3]);
  }

  float* ob = out + (size_t)b * CN*HN*WN;
  #pragma unroll
  for (int c = 0; c < CN; c++){
    *(u64*)(ob + ((size_t)c*HN + y0 + tpy     )*WN + col0) = outA[c];
    *(u64*)(ob + ((size_t)c*HN + y0 + tpy + 16)*WN + col0) = outB[c];
  }
}

extern "C" void kernel_launch(void* const* d_in, const int* in_sizes, int n_in,
                              void* d_out, int out_size)
{
  /* map inputs defensively by element count (all counts are distinct) */
  const float *x=0, *W1=0, *b1=0, *W2=0, *b2=0;
  for (int i = 0; i < n_in; i++){
    switch (in_sizes[i]){
      case BN*CN*HN*WN: x  = (const float*)d_in[i]; break;  /* 16777216 */
      case HID*4*CN:    W1 = (const float*)d_in[i]; break;  /* 512 */
      case HID:         b1 = (const float*)d_in[i]; break;  /* 32 */
      case CN*HID:      W2 = (const float*)d_in[i]; break;  /* 128 */
      case CN:          b2 = (const float*)d_in[i]; break;  /* 4 */
      default: break;
    }
  }
  dim3 grid(WN/TILE, HN/TILE, BN);   /* 16 x 16 x 16 */
  lee_kernel<<<grid, 256>>>(x, W1, b1, W2, b2, (float*)d_out);
}

// round 3
// speedup vs baseline: 1.0781x; 1.0781x over previous
#include <cuda_runtime.h>

typedef unsigned long long u64;

#define BN 16
#define CN 4
#define HN 512
#define WN 512
#define HID 32
#define TX 32
#define TY 16
#define RAD 3
#define RH (TY + 2*RAD)      /* 22 rows of horizontal sums */
#define NCP (TX/2)           /* 16 column pairs */

/* ---------------- f32x2 helpers (sm_100+ packed fp32) ---------------- */
__device__ __forceinline__ u64 pk(float lo, float hi){ u64 r; asm("mov.b64 %0,{%1,%2};":"=l"(r):"f"(lo),"f"(hi)); return r; }
__device__ __forceinline__ void upk(u64 v,float&lo,float&hi){ asm("mov.b64 {%0,%1},%2;":"=f"(lo),"=f"(hi):"l"(v)); }
__device__ __forceinline__ u64 dup2(float x){ u64 r; asm("mov.b64 %0,{%1,%1};":"=l"(r):"f"(x)); return r; }
__device__ __forceinline__ u64 ffma2(u64 a,u64 b,u64 c){ u64 d; asm("fma.rn.f32x2 %0,%1,%2,%3;":"=l"(d):"l"(a),"l"(b),"l"(c)); return d; }
__device__ __forceinline__ u64 fadd2(u64 a,u64 b){ u64 d; asm("add.rn.f32x2 %0,%1,%2;":"=l"(d):"l"(a),"l"(b)); return d; }
__device__ __forceinline__ u64 fmul2(u64 a,u64 b){ u64 d; asm("mul.rn.f32x2 %0,%1,%2;":"=l"(d):"l"(a),"l"(b)); return d; }
__device__ __forceinline__ float rcpf(float x){ float r; asm("rcp.approx.ftz.f32 %0,%1;":"=f"(r):"f"(x)); return r; }
__device__ __forceinline__ float ex2f(float x){ float r; asm("ex2.approx.ftz.f32 %0,%1;":"=f"(r):"f"(x)); return r; }

/* exact-gelu on a packed pair: x*0.5*(1+erf(x/sqrt2)), erf via A&S 7.1.26 */
__device__ __forceinline__ u64 gelu2(u64 h){
  const u64 SGN = 0x8000000080000000ULL;
  const u64 ABS = 0x7FFFFFFF7FFFFFFFULL;
  u64 az  = h & ABS;
  u64 azs = fmul2(az, dup2(0.70710678118654752f));
  u64 den = ffma2(azs, dup2(0.3275911f), dup2(1.0f));
  float d0,d1; upk(den,d0,d1);
  u64 t = pk(rcpf(d0), rcpf(d1));
  u64 P = ffma2(dup2(1.061405429f), t, dup2(-1.453152027f));
  P = ffma2(P, t, dup2(1.421413741f));
  P = ffma2(P, t, dup2(-0.284496736f));
  P = ffma2(P, t, dup2(0.254829592f));
  P = fmul2(P, t);
  u64 h2 = fmul2(h, h);
  u64 ea = fmul2(h2, dup2(-0.72134752044448170f));
  float e0,e1; upk(ea,e0,e1);
  u64 E  = pk(ex2f(e0), ex2f(e1));
  u64 PE = fmul2(P, E);
  u64 y  = ffma2(PE, dup2(-1.0f), dup2(1.0f));
  u64 er = y | (h & SGN);
  u64 u  = ffma2(er, dup2(0.5f), dup2(0.5f));
  return fmul2(h, u);
}

__device__ __forceinline__ int refl(int i, int n){
  if (i < 0) i = -i;
  if (i >= n) i = 2*n - 2 - i;
  return i;
}

__global__ void __launch_bounds__(256,3)
lee_kernel(const float* __restrict__ x, const float* __restrict__ W1,
           const float* __restrict__ b1, const float* __restrict__ W2,
           const float* __restrict__ b2, float* __restrict__ out)
{
  __shared__ __align__(16) u64 hsp[CN][RH][NCP];   /* packed horiz 7-sums of x   */
  __shared__ __align__(16) u64 hqp[CN][RH][NCP];   /* packed horiz 7-sums of x^2 */
  __shared__ __align__(16) u64 w1d[HID][16];       /* dup-packed weights */
  __shared__ __align__(16) u64 w2d[HID][CN];
  __shared__ __align__(16) u64 b1d[HID];
  __shared__ __align__(16) u64 b2d[CN];

  const int tid = threadIdx.x;
  const int x0 = blockIdx.x * TX;
  const int y0 = blockIdx.y * TY;
  const int b  = blockIdx.z;
  const float* xb = x + (size_t)b * CN * HN * WN;

  /* ---- weights -> dup-packed shared ---- */
  for (int i = tid; i < HID*16; i += 256){ float v = W1[i]; w1d[i>>4][i&15] = pk(v,v); }
  if (tid < HID*CN){ int k = tid >> 2, c = tid & 3; float v = W2[c*HID + k]; w2d[k][c] = pk(v,v); }
  if (tid < HID){ float v = b1[tid]; b1d[tid] = pk(v,v); }
  if (tid < CN){ float v = b2[tid]; b2d[tid] = pk(v,v); }

  /* ---- stage 1: horizontal 7-window running sums, 4 columns per item ---- */
  const bool ix = (x0 >= RAD) && (x0 + TX + RAD <= WN);
  for (int t = tid; t < CN*RH*8; t += 256){
    int c = t & 3;
    int g = (t >> 2) & 7;            /* group of 4 output columns */
    int r = t >> 5;                  /* 0..21 */
    int gy = refl(y0 - RAD + r, HN);
    const float* row = xb + ((size_t)c*HN + gy) * WN;
    int base = x0 + 4*g - RAD;       /* first needed column */
    float v[10];
    if (ix){
      const float4* p = (const float4*)(row + base - 1);   /* 16B aligned */
      float4 f0 = __ldg(p), f1 = __ldg(p+1), f2 = __ldg(p+2);
      v[0]=f0.y; v[1]=f0.z; v[2]=f0.w; v[3]=f1.x; v[4]=f1.y;
      v[5]=f1.z; v[6]=f1.w; v[7]=f2.x; v[8]=f2.y; v[9]=f2.z;
    } else {
      #pragma unroll
      for (int d = 0; d < 10; d++) v[d] = __ldg(row + refl(base + d, WN));
    }
    float s0 = ((v[0]+v[1])+(v[2]+v[3])) + ((v[4]+v[5])+v[6]);
    float s1 = s0 + (v[7]-v[0]);
    float s2 = s1 + (v[8]-v[1]);
    float s3 = s2 + (v[9]-v[2]);
    float w[10];
    #pragma unroll
    for (int d = 0; d < 10; d++) w[d] = v[d]*v[d];
    float q0 = ((w[0]+w[1])+(w[2]+w[3])) + ((w[4]+w[5])+w[6]);
    float q1 = q0 + (w[7]-w[0]);
    float q2 = q1 + (w[8]-w[1]);
    float q3 = q2 + (w[9]-w[2]);
    hsp[c][r][2*g]   = pk(s0,s1);
    hsp[c][r][2*g+1] = pk(s2,s3);
    hqp[c][r][2*g]   = pk(q0,q1);
    hqp[c][r][2*g+1] = pk(q2,q3);
  }
  __syncthreads();

  /* ---- stage 2: vertical sums + per-pixel MLP, one packed pixel-pair/thread ---- */
  const int tpx = tid & (NCP-1);
  const int tpy = tid >> 4;          /* 0..15 */
  const int col0 = x0 + 2*tpx;
  const u64 INV49 = dup2(1.0f/49.0f);

  u64 feat[16];
  #pragma unroll
  for (int c = 0; c < CN; c++){
    u64 s = hsp[c][tpy][tpx], q = hqp[c][tpy][tpx];
    #pragma unroll
    for (int dy = 1; dy < 7; dy++){
      s = fadd2(s, hsp[c][tpy+dy][tpx]);
      q = fadd2(q, hqp[c][tpy+dy][tpx]);
    }
    u64 mean = fmul2(s, INV49);
    u64 msq  = fmul2(q, INV49);
    u64 var  = ffma2(mean, mean ^ 0x8000000080000000ULL, msq);
    { float a0,a1; upk(var,a0,a1); var = pk(fmaxf(a0,0.f), fmaxf(a1,0.f)); }
    feat[c]    = *(const u64*)(xb + ((size_t)c*HN + y0 + tpy)*WN + col0);
    feat[4+c]  = mean;
    feat[8+c]  = var;
    feat[12+c] = msq;
  }

  u64 acc[CN];
  #pragma unroll
  for (int c = 0; c < CN; c++) acc[c] = fadd2(feat[c], b2d[c]);   /* x + b2 */

  #pragma unroll 2
  for (int kk = 0; kk < HID; kk += 2){
    /* two hidden units at once, each with split (lo/hi) accumulators: 4 chains */
    u64 a0lo = b1d[kk],   a0hi = 0ULL;
    u64 a1lo = b1d[kk+1], a1hi = 0ULL;
    const ulonglong2* w0 = (const ulonglong2*)&w1d[kk][0];
    const ulonglong2* w1r = (const ulonglong2*)&w1d[kk+1][0];
    #pragma unroll
    for (int j = 0; j < 4; j++){
      ulonglong2 wa = w0[j], wb = w0[j+4], wc = w1r[j], wd = w1r[j+4];
      a0lo = ffma2(feat[2*j],   wa.x, a0lo);
      a0hi = ffma2(feat[8+2*j], wb.x, a0hi);
      a1lo = ffma2(feat[2*j],   wc.x, a1lo);
      a1hi = ffma2(feat[8+2*j], wd.x, a1hi);
      a0lo = ffma2(feat[2*j+1],   wa.y, a0lo);
      a0hi = ffma2(feat[8+2*j+1], wb.y, a0hi);
      a1lo = ffma2(feat[2*j+1],   wc.y, a1lo);
      a1hi = ffma2(feat[8+2*j+1], wd.y, a1hi);
    }
    u64 g0 = gelu2(fadd2(a0lo, a0hi));
    u64 g1 = gelu2(fadd2(a1lo, a1hi));
    const ulonglong2* w2a = (const ulonglong2*)&w2d[kk][0];
    const ulonglong2* w2b = (const ulonglong2*)&w2d[kk+1][0];
    ulonglong2 p0 = w2a[0], p1 = w2a[1], p2 = w2b[0], p3 = w2b[1];
    acc[0] = ffma2(g0, p0.x, acc[0]);  acc[0] = ffma2(g1, p2.x, acc[0]);
    acc[1] = ffma2(g0, p0.y, acc[1]);  acc[1] = ffma2(g1, p2.y, acc[1]);
    acc[2] = ffma2(g0, p1.x, acc[2]);  acc[2] = ffma2(g1, p3.x, acc[2]);
    acc[3] = ffma2(g0, p1.y, acc[3]);  acc[3] = ffma2(g1, p3.y, acc[3]);
  }

  float* ob = out + (size_t)b * CN*HN*WN;
  #pragma unroll
  for (int c = 0; c < CN; c++)
    *(u64*)(ob + ((size_t)c*HN + y0 + tpy)*WN + col0) = acc[c];
}

extern "C" void kernel_launch(void* const* d_in, const int* in_sizes, int n_in,
                              void* d_out, int out_size)
{
  const float *x=0, *W1=0, *b1=0, *W2=0, *b2=0;
  for (int i = 0; i < n_in; i++){
    switch (in_sizes[i]){
      case BN*CN*HN*WN: x  = (const float*)d_in[i]; break;
      case HID*4*CN:    W1 = (const float*)d_in[i]; break;
      case HID:         b1 = (const float*)d_in[i]; break;
      case CN*HID:      W2 = (const float*)d_in[i]; break;
      case CN:          b2 = (const float*)d_in[i]; break;
      default: break;
    }
  }
  dim3 grid(WN/TX, HN/TY, BN);   /* 16 x 32 x 16 */
  lee_kernel<<<grid, 256>>>(x, W1, b1, W2, b2, (float*)d_out);
}

// round 6
// speedup vs baseline: 1.1695x; 1.0847x over previous
#include <cuda_runtime.h>

typedef unsigned long long u64;

#define BN 16
#define CN 4
#define HN 512
#define WN 512
#define HID 32
#define TX 32
#define TY 32
#define RAD 3
#define RH (TY + 2*RAD)      /* 38 rows of horizontal sums */
#define NCP (TX/2)           /* 16 column pairs */

/* ---------------- f32x2 helpers (sm_100+ packed fp32) ---------------- */
__device__ __forceinline__ u64 pk(float lo, float hi){ u64 r; asm("mov.b64 %0,{%1,%2};":"=l"(r):"f"(lo),"f"(hi)); return r; }
__device__ __forceinline__ void upk(u64 v,float&lo,float&hi){ asm("mov.b64 {%0,%1},%2;":"=f"(lo),"=f"(hi):"l"(v)); }
__device__ __forceinline__ u64 dup2(float x){ u64 r; asm("mov.b64 %0,{%1,%1};":"=l"(r):"f"(x)); return r; }
__device__ __forceinline__ u64 ffma2(u64 a,u64 b,u64 c){ u64 d; asm("fma.rn.f32x2 %0,%1,%2,%3;":"=l"(d):"l"(a),"l"(b),"l"(c)); return d; }
__device__ __forceinline__ u64 fadd2(u64 a,u64 b){ u64 d; asm("add.rn.f32x2 %0,%1,%2;":"=l"(d):"l"(a),"l"(b)); return d; }
__device__ __forceinline__ u64 fmul2(u64 a,u64 b){ u64 d; asm("mul.rn.f32x2 %0,%1,%2;":"=l"(d):"l"(a),"l"(b)); return d; }
__device__ __forceinline__ float rcpf(float x){ float r; asm("rcp.approx.ftz.f32 %0,%1;":"=f"(r):"f"(x)); return r; }
__device__ __forceinline__ float ex2f(float x){ float r; asm("ex2.approx.ftz.f32 %0,%1;":"=f"(r):"f"(x)); return r; }

#define SGNM 0x8000000080000000ULL

/* exact-gelu on a packed pair: x*0.5*(1+erf(x/sqrt2)), erf via A&S 7.1.26 */
__device__ __forceinline__ u64 gelu2(u64 h){
  const u64 ABS = 0x7FFFFFFF7FFFFFFFULL;
  u64 az  = h & ABS;
  u64 azs = fmul2(az, dup2(0.70710678118654752f));
  u64 den = ffma2(azs, dup2(0.3275911f), dup2(1.0f));
  float d0,d1; upk(den,d0,d1);
  u64 t = pk(rcpf(d0), rcpf(d1));
  u64 P = ffma2(dup2(1.061405429f), t, dup2(-1.453152027f));
  P = ffma2(P, t, dup2(1.421413741f));
  P = ffma2(P, t, dup2(-0.284496736f));
  P = ffma2(P, t, dup2(0.254829592f));
  P = fmul2(P, t);
  u64 h2 = fmul2(h, h);
  u64 ea = fmul2(h2, dup2(-0.72134752044448170f));
  float e0,e1; upk(ea,e0,e1);
  u64 E  = pk(ex2f(e0), ex2f(e1));
  u64 PE = fmul2(P, E);
  u64 y  = ffma2(PE, dup2(-1.0f), dup2(1.0f));
  u64 er = y | (h & SGNM);
  u64 u  = ffma2(er, dup2(0.5f), dup2(0.5f));
  return fmul2(h, u);
}

__device__ __forceinline__ int refl(int i, int n){
  if (i < 0) i = -i;
  if (i >= n) i = 2*n - 2 - i;
  return i;
}

__global__ void __launch_bounds__(256,2)
lee_kernel(const float* __restrict__ x, const float* __restrict__ W1,
           const float* __restrict__ b1, const float* __restrict__ W2,
           const float* __restrict__ b2, float* __restrict__ out)
{
  /* horiz 7-sums (stage 1) -> converted IN PLACE to full 7x7 sums (stage 1.5) */
  __shared__ __align__(16) u64 hsp[CN][RH][NCP];
  __shared__ __align__(16) u64 hqp[CN][RH][NCP];
  __shared__ __align__(16) u64 w1d[HID][16];       /* dup-packed weights */
  __shared__ __align__(16) u64 w2d[HID][CN];
  __shared__ __align__(16) u64 b1d[HID];
  __shared__ __align__(16) u64 b2d[CN];

  const int tid = threadIdx.x;
  const int x0 = blockIdx.x * TX;
  const int y0 = blockIdx.y * TY;
  const int b  = blockIdx.z;
  const float* xb = x + (size_t)b * CN * HN * WN;

  /* ---- weights -> dup-packed shared ---- */
  for (int i = tid; i < HID*16; i += 256){ float v = W1[i]; w1d[i>>4][i&15] = pk(v,v); }
  if (tid < HID*CN){ int k = tid >> 2, c = tid & 3; float v = W2[c*HID + k]; w2d[k][c] = pk(v,v); }
  if (tid < HID){ float v = b1[tid]; b1d[tid] = pk(v,v); }
  if (tid < CN){ float v = b2[tid]; b2d[tid] = pk(v,v); }

  /* ---- stage 1: horizontal 7-window running sums, 4 columns per item ---- */
  const bool ix = (x0 >= RAD) && (x0 + TX + RAD <= WN);
  for (int t = tid; t < CN*RH*8; t += 256){
    int c = t & 3;
    int g = (t >> 2) & 7;            /* group of 4 output columns */
    int r = t >> 5;                  /* 0..37 */
    int gy = refl(y0 - RAD + r, HN);
    const float* row = xb + ((size_t)c*HN + gy) * WN;
    int base = x0 + 4*g - RAD;
    float v[10];
    if (ix){
      const float4* p = (const float4*)(row + base - 1);   /* 16B aligned */
      float4 f0 = __ldg(p), f1 = __ldg(p+1), f2 = __ldg(p+2);
      v[0]=f0.y; v[1]=f0.z; v[2]=f0.w; v[3]=f1.x; v[4]=f1.y;
      v[5]=f1.z; v[6]=f1.w; v[7]=f2.x; v[8]=f2.y; v[9]=f2.z;
    } else {
      #pragma unroll
      for (int d = 0; d < 10; d++) v[d] = __ldg(row + refl(base + d, WN));
    }
    float s0 = ((v[0]+v[1])+(v[2]+v[3])) + ((v[4]+v[5])+v[6]);
    float s1 = s0 + (v[7]-v[0]);
    float s2 = s1 + (v[8]-v[1]);
    float s3 = s2 + (v[9]-v[2]);
    float w[10];
    #pragma unroll
    for (int d = 0; d < 10; d++) w[d] = v[d]*v[d];
    float q0 = ((w[0]+w[1])+(w[2]+w[3])) + ((w[4]+w[5])+w[6]);
    float q1 = q0 + (w[7]-w[0]);
    float q2 = q1 + (w[8]-w[1]);
    float q3 = q2 + (w[9]-w[2]);
    hsp[c][r][2*g]   = pk(s0,s1);
    hsp[c][r][2*g+1] = pk(s2,s3);
    hqp[c][r][2*g]   = pk(q0,q1);
    hqp[c][r][2*g+1] = pk(q2,q3);
  }
  __syncthreads();

  /* ---- stage 1.5: vertical 7-sums IN PLACE (regs-first, barrier, write) ----
     Each thread owns (c, column-pair, 8-row chunk): loads 14 horiz-sum rows,
     then overwrites rows [8q, 8q+7] with the full 7x7 window sums. */
  {
    int c  = tid & 3;
    int px = (tid >> 2) & 15;
    int qy = tid >> 6;               /* 0..3 -> rows 8qy..8qy+7 */
    u64 rs[14], rq[14];
    #pragma unroll
    for (int j = 0; j < 14; j++){ rs[j] = hsp[c][8*qy + j][px]; rq[j] = hqp[c][8*qy + j][px]; }
    __syncthreads();                 /* everyone captured inputs before any write */
    u64 s = fadd2(fadd2(fadd2(rs[0],rs[1]), fadd2(rs[2],rs[3])), fadd2(fadd2(rs[4],rs[5]), rs[6]));
    u64 q = fadd2(fadd2(fadd2(rq[0],rq[1]), fadd2(rq[2],rq[3])), fadd2(fadd2(rq[4],rq[5]), rq[6]));
    hsp[c][8*qy][px] = s;
    hqp[c][8*qy][px] = q;
    #pragma unroll
    for (int i = 1; i < 8; i++){
      s = fadd2(s, fadd2(rs[i+6], rs[i-1] ^ SGNM));
      q = fadd2(q, fadd2(rq[i+6], rq[i-1] ^ SGNM));
      hsp[c][8*qy + i][px] = s;
      hqp[c][8*qy + i][px] = q;
    }
  }
  __syncthreads();

  /* ---- stage 2: two vertically-adjacent pixel-pairs per thread + MLP ---- */
  const int tpx = tid & (NCP-1);
  const int ty2 = tid >> 4;          /* 0..15 -> rows 2*ty2, 2*ty2+1 */
  const int yA = 2*ty2, yB = 2*ty2 + 1;
  const int col0 = x0 + 2*tpx;
  const u64 INV49 = dup2(1.0f/49.0f);

  u64 featA[16], featB[16];
  #pragma unroll
  for (int c = 0; c < CN; c++){
    u64 sA = hsp[c][yA][tpx], qA = hqp[c][yA][tpx];
    u64 sB = hsp[c][yB][tpx], qB = hqp[c][yB][tpx];
    u64 meanA = fmul2(sA, INV49), msqA = fmul2(qA, INV49);
    u64 meanB = fmul2(sB, INV49), msqB = fmul2(qB, INV49);
    u64 varA = ffma2(meanA, meanA ^ SGNM, msqA);
    u64 varB = ffma2(meanB, meanB ^ SGNM, msqB);
    { float a0,a1; upk(varA,a0,a1); varA = pk(fmaxf(a0,0.f), fmaxf(a1,0.f)); }
    { float a0,a1; upk(varB,a0,a1); varB = pk(fmaxf(a0,0.f), fmaxf(a1,0.f)); }
    featA[c]    = *(const u64*)(xb + ((size_t)c*HN + y0 + yA)*WN + col0);
    featB[c]    = *(const u64*)(xb + ((size_t)c*HN + y0 + yB)*WN + col0);
    featA[4+c]  = meanA;  featB[4+c]  = meanB;
    featA[8+c]  = varA;   featB[8+c]  = varB;
    featA[12+c] = msqA;   featB[12+c] = msqB;
  }

  u64 accA[CN], accB[CN];
  #pragma unroll
  for (int c = 0; c < CN; c++){
    accA[c] = fadd2(featA[c], b2d[c]);
    accB[c] = fadd2(featB[c], b2d[c]);
  }

  #pragma unroll 2
  for (int kk = 0; kk < HID; kk += 2){
    u64 aA0 = b1d[kk],   aB0 = b1d[kk];
    u64 aA1 = b1d[kk+1], aB1 = b1d[kk+1];
    const ulonglong2* w0  = (const ulonglong2*)&w1d[kk][0];
    const ulonglong2* w1r = (const ulonglong2*)&w1d[kk+1][0];
    #pragma unroll
    for (int j = 0; j < 8; j++){
      ulonglong2 wa = w0[j], wb = w1r[j];
      aA0 = ffma2(featA[2*j],   wa.x, aA0);
      aB0 = ffma2(featB[2*j],   wa.x, aB0);
      aA1 = ffma2(featA[2*j],   wb.x, aA1);
      aB1 = ffma2(featB[2*j],   wb.x, aB1);
      aA0 = ffma2(featA[2*j+1], wa.y, aA0);
      aB0 = ffma2(featB[2*j+1], wa.y, aB0);
      aA1 = ffma2(featA[2*j+1], wb.y, aA1);
      aB1 = ffma2(featB[2*j+1], wb.y, aB1);
    }
    u64 gA0 = gelu2(aA0), gB0 = gelu2(aB0);
    u64 gA1 = gelu2(aA1), gB1 = gelu2(aB1);
    const ulonglong2* w2a = (const ulonglong2*)&w2d[kk][0];
    const ulonglong2* w2b = (const ulonglong2*)&w2d[kk+1][0];
    ulonglong2 p0 = w2a[0], p1 = w2a[1], p2 = w2b[0], p3 = w2b[1];
    accA[0] = ffma2(gA0, p0.x, accA[0]);  accA[0] = ffma2(gA1, p2.x, accA[0]);
    accB[0] = ffma2(gB0, p0.x, accB[0]);  accB[0] = ffma2(gB1, p2.x, accB[0]);
    accA[1] = ffma2(gA0, p0.y, accA[1]);  accA[1] = ffma2(gA1, p2.y, accA[1]);
    accB[1] = ffma2(gB0, p0.y, accB[1]);  accB[1] = ffma2(gB1, p2.y, accB[1]);
    accA[2] = ffma2(gA0, p1.x, accA[2]);  accA[2] = ffma2(gA1, p3.x, accA[2]);
    accB[2] = ffma2(gB0, p1.x, accB[2]);  accB[2] = ffma2(gB1, p3.x, accB[2]);
    accA[3] = ffma2(gA0, p1.y, accA[3]);  accA[3] = ffma2(gA1, p3.y, accA[3]);
    accB[3] = ffma2(gB0, p1.y, accB[3]);  accB[3] = ffma2(gB1, p3.y, accB[3]);
  }

  float* ob = out + (size_t)b * CN*HN*WN;
  #pragma unroll
  for (int c = 0; c < CN; c++){
    *(u64*)(ob + ((size_t)c*HN + y0 + yA)*WN + col0) = accA[c];
    *(u64*)(ob + ((size_t)c*HN + y0 + yB)*WN + col0) = accB[c];
  }
}

extern "C" void kernel_launch(void* const* d_in, const int* in_sizes, int n_in,
                              void* d_out, int out_size)
{
  const float *x=0, *W1=0, *b1=0, *W2=0, *b2=0;
  for (int i = 0; i < n_in; i++){
    switch (in_sizes[i]){
      case BN*CN*HN*WN: x  = (const float*)d_in[i]; break;
      case HID*4*CN:    W1 = (const float*)d_in[i]; break;
      case HID:         b1 = (const float*)d_in[i]; break;
      case CN*HID:      W2 = (const float*)d_in[i]; break;
      case CN:          b2 = (const float*)d_in[i]; break;
      default: break;
    }
  }
  dim3 grid(WN/TX, HN/TY, BN);   /* 16 x 16 x 16 */
  lee_kernel<<<grid, 256>>>(x, W1, b1, W2, b2, (float*)d_out);
}

// round 8
// speedup vs baseline: 1.2644x; 1.0812x over previous
#include <cuda_runtime.h>

typedef unsigned long long u64;

#define BN 16
#define CN 4
#define HN 512
#define WN 512
#define HID 32
#define TX 32
#define TY 32
#define RAD 3
#define RH (TY + 2*RAD)      /* 38 rows of horizontal sums */
#define NCP (TX/2)           /* 16 column pairs */

/* ---------------- f32x2 helpers (sm_100+ packed fp32) ---------------- */
__device__ __forceinline__ u64 pk(float lo, float hi){ u64 r; asm("mov.b64 %0,{%1,%2};":"=l"(r):"f"(lo),"f"(hi)); return r; }
__device__ __forceinline__ void upk(u64 v,float&lo,float&hi){ asm("mov.b64 {%0,%1},%2;":"=f"(lo),"=f"(hi):"l"(v)); }
__device__ __forceinline__ u64 dup2(float x){ u64 r; asm("mov.b64 %0,{%1,%1};":"=l"(r):"f"(x)); return r; }
__device__ __forceinline__ u64 ffma2(u64 a,u64 b,u64 c){ u64 d; asm("fma.rn.f32x2 %0,%1,%2,%3;":"=l"(d):"l"(a),"l"(b),"l"(c)); return d; }
__device__ __forceinline__ u64 fadd2(u64 a,u64 b){ u64 d; asm("add.rn.f32x2 %0,%1,%2;":"=l"(d):"l"(a),"l"(b)); return d; }
__device__ __forceinline__ u64 fmul2(u64 a,u64 b){ u64 d; asm("mul.rn.f32x2 %0,%1,%2;":"=l"(d):"l"(a),"l"(b)); return d; }
__device__ __forceinline__ float rcpf(float x){ float r; asm("rcp.approx.ftz.f32 %0,%1;":"=f"(r):"f"(x)); return r; }
__device__ __forceinline__ float ex2f(float x){ float r; asm("ex2.approx.ftz.f32 %0,%1;":"=f"(r):"f"(x)); return r; }

#define SGNM 0x8000000080000000ULL

/* tanh-form gelu on a packed pair:
   g = h - h*r,  r = 1/(1 + exp(2t)),  t = sqrt(2/pi)*(h + 0.044715 h^3)
   exponent computed directly in base-2: e2t = ex2(h*(C1 + C2*h^2)),
   C1 = 2*log2(e)*0.7978845608, C2 = C1*0.044715.
   Saturates cleanly: +inf -> r=0 -> g=h ; 0 -> r=1 -> g=0. */
__device__ __forceinline__ u64 gelu2(u64 h){
  u64 h2   = fmul2(h, h);
  u64 s    = ffma2(h2, dup2(0.10294456f), dup2(2.3022077f));
  u64 targ = fmul2(h, s);
  float t0,t1; upk(targ,t0,t1);
  u64 E    = pk(ex2f(t0), ex2f(t1));
  u64 den  = fadd2(E, dup2(1.0f));
  float d0,d1; upk(den,d0,d1);
  u64 r    = pk(rcpf(d0), rcpf(d1));
  u64 m    = fmul2(h, r);
  return fadd2(h, m ^ SGNM);     /* h - h*r */
}

__device__ __forceinline__ int refl(int i, int n){
  if (i < 0) i = -i;
  if (i >= n) i = 2*n - 2 - i;
  return i;
}

__global__ void __launch_bounds__(256,2)
lee_kernel(const float* __restrict__ x, const float* __restrict__ W1,
           const float* __restrict__ b1, const float* __restrict__ W2,
           const float* __restrict__ b2, float* __restrict__ out)
{
  /* horiz 7-sums (stage 1) -> converted IN PLACE to full 7x7 sums (stage 1.5) */
  __shared__ __align__(16) u64 hsp[CN][RH][NCP];
  __shared__ __align__(16) u64 hqp[CN][RH][NCP];
  __shared__ __align__(16) u64 w1d[HID][16];       /* dup-packed weights */
  __shared__ __align__(16) u64 w2d[HID][CN];
  __shared__ __align__(16) u64 b1d[HID];
  __shared__ __align__(16) u64 b2d[CN];

  const int tid = threadIdx.x;
  const int x0 = blockIdx.x * TX;
  const int y0 = blockIdx.y * TY;
  const int b  = blockIdx.z;
  const float* xb = x + (size_t)b * CN * HN * WN;

  /* ---- weights -> dup-packed shared ---- */
  for (int i = tid; i < HID*16; i += 256){ float v = W1[i]; w1d[i>>4][i&15] = pk(v,v); }
  if (tid < HID*CN){ int k = tid >> 2, c = tid & 3; float v = W2[c*HID + k]; w2d[k][c] = pk(v,v); }
  if (tid < HID){ float v = b1[tid]; b1d[tid] = pk(v,v); }
  if (tid < CN){ float v = b2[tid]; b2d[tid] = pk(v,v); }

  /* ---- stage 1: horizontal 7-window running sums, 4 columns per item ---- */
  const bool ix = (x0 >= RAD) && (x0 + TX + RAD <= WN);
  for (int t = tid; t < CN*RH*8; t += 256){
    int c = t & 3;
    int g = (t >> 2) & 7;            /* group of 4 output columns */
    int r = t >> 5;                  /* 0..37 */
    int gy = refl(y0 - RAD + r, HN);
    const float* row = xb + ((size_t)c*HN + gy) * WN;
    int base = x0 + 4*g - RAD;
    float v[10];
    if (ix){
      const float4* p = (const float4*)(row + base - 1);   /* 16B aligned */
      float4 f0 = __ldg(p), f1 = __ldg(p+1), f2 = __ldg(p+2);
      v[0]=f0.y; v[1]=f0.z; v[2]=f0.w; v[3]=f1.x; v[4]=f1.y;
      v[5]=f1.z; v[6]=f1.w; v[7]=f2.x; v[8]=f2.y; v[9]=f2.z;
    } else {
      #pragma unroll
      for (int d = 0; d < 10; d++) v[d] = __ldg(row + refl(base + d, WN));
    }
    float s0 = ((v[0]+v[1])+(v[2]+v[3])) + ((v[4]+v[5])+v[6]);
    float s1 = s0 + (v[7]-v[0]);
    float s2 = s1 + (v[8]-v[1]);
    float s3 = s2 + (v[9]-v[2]);
    float w[10];
    #pragma unroll
    for (int d = 0; d < 10; d++) w[d] = v[d]*v[d];
    float q0 = ((w[0]+w[1])+(w[2]+w[3])) + ((w[4]+w[5])+w[6]);
    float q1 = q0 + (w[7]-w[0]);
    float q2 = q1 + (w[8]-w[1]);
    float q3 = q2 + (w[9]-w[2]);
    hsp[c][r][2*g]   = pk(s0,s1);
    hsp[c][r][2*g+1] = pk(s2,s3);
    hqp[c][r][2*g]   = pk(q0,q1);
    hqp[c][r][2*g+1] = pk(q2,q3);
  }
  __syncthreads();

  /* ---- stage 1.5: vertical 7-sums IN PLACE (regs-first, barrier, write) ---- */
  {
    int c  = tid & 3;
    int px = (tid >> 2) & 15;
    int qy = tid >> 6;               /* 0..3 -> rows 8qy..8qy+7 */
    u64 rs[14], rq[14];
    #pragma unroll
    for (int j = 0; j < 14; j++){ rs[j] = hsp[c][8*qy + j][px]; rq[j] = hqp[c][8*qy + j][px]; }
    __syncthreads();                 /* everyone captured inputs before any write */
    u64 s = fadd2(fadd2(fadd2(rs[0],rs[1]), fadd2(rs[2],rs[3])), fadd2(fadd2(rs[4],rs[5]), rs[6]));
    u64 q = fadd2(fadd2(fadd2(rq[0],rq[1]), fadd2(rq[2],rq[3])), fadd2(fadd2(rq[4],rq[5]), rq[6]));
    hsp[c][8*qy][px] = s;
    hqp[c][8*qy][px] = q;
    #pragma unroll
    for (int i = 1; i < 8; i++){
      s = fadd2(s, fadd2(rs[i+6], rs[i-1] ^ SGNM));
      q = fadd2(q, fadd2(rq[i+6], rq[i-1] ^ SGNM));
      hsp[c][8*qy + i][px] = s;
      hqp[c][8*qy + i][px] = q;
    }
  }
  __syncthreads();

  /* ---- stage 2: two vertically-adjacent pixel-pairs per thread + MLP ---- */
  const int tpx = tid & (NCP-1);
  const int ty2 = tid >> 4;          /* 0..15 -> rows 2*ty2, 2*ty2+1 */
  const int yA = 2*ty2, yB = 2*ty2 + 1;
  const int col0 = x0 + 2*tpx;
  const u64 INV49 = dup2(1.0f/49.0f);

  u64 featA[16], featB[16];
  #pragma unroll
  for (int c = 0; c < CN; c++){
    u64 sA = hsp[c][yA][tpx], qA = hqp[c][yA][tpx];
    u64 sB = hsp[c][yB][tpx], qB = hqp[c][yB][tpx];
    u64 meanA = fmul2(sA, INV49), msqA = fmul2(qA, INV49);
    u64 meanB = fmul2(sB, INV49), msqB = fmul2(qB, INV49);
    u64 varA = ffma2(meanA, meanA ^ SGNM, msqA);
    u64 varB = ffma2(meanB, meanB ^ SGNM, msqB);
    { float a0,a1; upk(varA,a0,a1); varA = pk(fmaxf(a0,0.f), fmaxf(a1,0.f)); }
    { float a0,a1; upk(varB,a0,a1); varB = pk(fmaxf(a0,0.f), fmaxf(a1,0.f)); }
    featA[c]    = *(const u64*)(xb + ((size_t)c*HN + y0 + yA)*WN + col0);
    featB[c]    = *(const u64*)(xb + ((size_t)c*HN + y0 + yB)*WN + col0);
    featA[4+c]  = meanA;  featB[4+c]  = meanB;
    featA[8+c]  = varA;   featB[8+c]  = varB;
    featA[12+c] = msqA;   featB[12+c] = msqB;
  }

  u64 accA[CN], accB[CN];
  #pragma unroll
  for (int c = 0; c < CN; c++){
    accA[c] = fadd2(featA[c], b2d[c]);
    accB[c] = fadd2(featB[c], b2d[c]);
  }

  #pragma unroll 2
  for (int kk = 0; kk < HID; kk += 2){
    u64 aA0 = b1d[kk],   aB0 = b1d[kk];
    u64 aA1 = b1d[kk+1], aB1 = b1d[kk+1];
    const ulonglong2* w0  = (const ulonglong2*)&w1d[kk][0];
    const ulonglong2* w1r = (const ulonglong2*)&w1d[kk+1][0];
    #pragma unroll
    for (int j = 0; j < 8; j++){
      ulonglong2 wa = w0[j], wb = w1r[j];
      aA0 = ffma2(featA[2*j],   wa.x, aA0);
      aB0 = ffma2(featB[2*j],   wa.x, aB0);
      aA1 = ffma2(featA[2*j],   wb.x, aA1);
      aB1 = ffma2(featB[2*j],   wb.x, aB1);
      aA0 = ffma2(featA[2*j+1], wa.y, aA0);
      aB0 = ffma2(featB[2*j+1], wa.y, aB0);
      aA1 = ffma2(featA[2*j+1], wb.y, aA1);
      aB1 = ffma2(featB[2*j+1], wb.y, aB1);
    }
    u64 gA0 = gelu2(aA0), gB0 = gelu2(aB0);
    u64 gA1 = gelu2(aA1), gB1 = gelu2(aB1);
    const ulonglong2* w2a = (const ulonglong2*)&w2d[kk][0];
    const ulonglong2* w2b = (const ulonglong2*)&w2d[kk+1][0];
    ulonglong2 p0 = w2a[0], p1 = w2a[1], p2 = w2b[0], p3 = w2b[1];
    accA[0] = ffma2(gA0, p0.x, accA[0]);  accA[0] = ffma2(gA1, p2.x, accA[0]);
    accB[0] = ffma2(gB0, p0.x, accB[0]);  accB[0] = ffma2(gB1, p2.x, accB[0]);
    accA[1] = ffma2(gA0, p0.y, accA[1]);  accA[1] = ffma2(gA1, p2.y, accA[1]);
    accB[1] = ffma2(gB0, p0.y, accB[1]);  accB[1] = ffma2(gB1, p2.y, accB[1]);
    accA[2] = ffma2(gA0, p1.x, accA[2]);  accA[2] = ffma2(gA1, p3.x, accA[2]);
    accB[2] = ffma2(gB0, p1.x, accB[2]);  accB[2] = ffma2(gB1, p3.x, accB[2]);
    accA[3] = ffma2(gA0, p1.y, accA[3]);  accA[3] = ffma2(gA1, p3.y, accA[3]);
    accB[3] = ffma2(gB0, p1.y, accB[3]);  accB[3] = ffma2(gB1, p3.y, accB[3]);
  }

  float* ob = out + (size_t)b * CN*HN*WN;
  #pragma unroll
  for (int c = 0; c < CN; c++){
    *(u64*)(ob + ((size_t)c*HN + y0 + yA)*WN + col0) = accA[c];
    *(u64*)(ob + ((size_t)c*HN + y0 + yB)*WN + col0) = accB[c];
  }
}

extern "C" void kernel_launch(void* const* d_in, const int* in_sizes, int n_in,
                              void* d_out, int out_size)
{
  const float *x=0, *W1=0, *b1=0, *W2=0, *b2=0;
  for (int i = 0; i < n_in; i++){
    switch (in_sizes[i]){
      case BN*CN*HN*WN: x  = (const float*)d_in[i]; break;
      case HID*4*CN:    W1 = (const float*)d_in[i]; break;
      case HID:         b1 = (const float*)d_in[i]; break;
      case CN*HID:      W2 = (const float*)d_in[i]; break;
      case CN:          b2 = (const float*)d_in[i]; break;
      default: break;
    }
  }
  dim3 grid(WN/TX, HN/TY, BN);   /* 16 x 16 x 16 */
  lee_kernel<<<grid, 256>>>(x, W1, b1, W2, b2, (float*)d_out);
}